// round 12
// baseline (speedup 1.0000x reference)
#include <cuda_runtime.h>
#include <cstdint>

#define NV_P   32
#define C_VX   0.16f
#define C_VY   0.16f
#define C_VZ   4.0f
#define C_XOFF 0.08f
#define C_YOFF -39.6f
#define C_ZOFF -1.0f
#define BN_EPS 1e-3f

#define KF_BLOCKS  592
#define KF_THREADS 256
#define K1B_BLOCKS 148
#define GP_W       592
#define NSTAT      65
// g_stat layout (same as validated R11):
// [0..9] M2 (xx,xy,xz,xw,yy,yz,yw,zz,zw,ww)  [10..13] m1(x,y,z,w)
// [14..37] X[a][k]=Σ m1_v[a]*q_v[k]  [38..58] Y tri=Σ cnt q q  [59..64] z=Σ cnt q
// q = (mx,my,mz,cx,cy,cz)

// -------- global scratch (allocation-free rule: __device__ globals) --------
__device__ float  g_part[NSTAT * GP_W];
__device__ double g_stat[NSTAT];
__device__ float4 g_kw4[128];        // per-channel: (sw4,sw5,sw6,sw7),(sw8,sw9,|a|,b)
__device__ float4 g_mean[131072];    // per-voxel (mx,my,mz,cnt)
__device__ float4 g_m1[131072];      // per-voxel masked raw sums (x,y,z,w)

// ---------------- packed f32x2 helpers ----------------
__device__ __forceinline__ unsigned long long pk2(float lo, float hi) {
    unsigned long long r;
    asm("mov.b64 %0, {%1, %2};" : "=l"(r) : "f"(lo), "f"(hi));
    return r;
}
__device__ __forceinline__ void unpk2(unsigned long long x, float& lo, float& hi) {
    asm("mov.b64 {%0, %1}, %2;" : "=f"(lo), "=f"(hi) : "l"(x));
}
__device__ __forceinline__ unsigned long long fma2(unsigned long long a, unsigned long long b, unsigned long long c) {
    unsigned long long d;
    asm("fma.rn.f32x2 %0, %1, %2, %3;" : "=l"(d) : "l"(a), "l"(b), "l"(c));
    return d;
}
__device__ __forceinline__ unsigned long long add2(unsigned long long a, unsigned long long b) {
    unsigned long long d;
    asm("add.rn.f32x2 %0, %1, %2;" : "=l"(d) : "l"(a), "l"(b));
    return d;
}
__device__ __forceinline__ unsigned long long mul2(unsigned long long a, unsigned long long b) {
    unsigned long long d;
    asm("mul.rn.f32x2 %0, %1, %2;" : "=l"(d) : "l"(a), "l"(b));
    return d;
}
// warp sum via integer REDUX (validated R10); fixed-point scale 2^22.
__device__ __forceinline__ float redux_sumf(float x) {
    int xi = __float2int_rn(x * 4194304.0f);
    int s;
    asm("redux.sync.add.s32 %0, %1, 0xffffffff;" : "=r"(s) : "r"(xi));
    return (float)s * 2.384185791015625e-7f;   // 1/2^22
}

// ---------------- kF: fused raw-max + raw-moment pass (single read of vf) ----------------
__global__ __launch_bounds__(KF_THREADS, 3) void kF(
    const float* __restrict__ vf, const int* __restrict__ vnp,
    const float* __restrict__ W, const float* __restrict__ gamma,
    float* __restrict__ out, int V)
{
    __shared__ __align__(16) float sh[8 * NV_P * 4];   // pair-transposed staging
    __shared__ float red[14 * 8];
    const int lane = threadIdx.x & 31;
    const int wib  = threadIdx.x >> 5;
    const int gw   = (blockIdx.x * blockDim.x + threadIdx.x) >> 5;
    const int nw   = (gridDim.x * blockDim.x) >> 5;
    float* msh = sh + wib * (NV_P * 4);

    // sign-folded point-packed channel weights (lane = channel pair), as R9
    const float* wA = W + (2 * lane) * 10;
    const float* wB = wA + 10;
    float sA = (gamma[2 * lane]     >= 0.f) ? 1.f : -1.f;
    float sB = (gamma[2 * lane + 1] >= 0.f) ? 1.f : -1.f;
    float uA0s = sA * (wA[0] + wA[4] + wA[7]);
    float uA1s = sA * (wA[1] + wA[5] + wA[8]);
    float uA2s = sA * (wA[2] + wA[6] + wA[9]);
    float uA3s = sA * wA[3];
    float uB0s = sB * (wB[0] + wB[4] + wB[7]);
    float uB1s = sB * (wB[1] + wB[5] + wB[8]);
    float uB2s = sB * (wB[2] + wB[6] + wB[9]);
    float uB3s = sB * wB[3];
    unsigned long long uA0 = pk2(uA0s, uA0s), uA1 = pk2(uA1s, uA1s);
    unsigned long long uA2 = pk2(uA2s, uA2s), uA3 = pk2(uA3s, uA3s);
    unsigned long long uB0 = pk2(uB0s, uB0s), uB1 = pk2(uB1s, uB1s);
    unsigned long long uB2 = pk2(uB2s, uB2s), uB3 = pk2(uB3s, uB3s);

    // global raw-moment accumulators (lane = point)
    unsigned long long M2a = 0ull, M2b = 0ull, M2c = 0ull, M2d = 0ull, M2e = 0ull;
    unsigned long long m1a = 0ull, m1b = 0ull;

    int v = gw;
    float4 pt; int cnt;
    if (v < V) {
        pt  = reinterpret_cast<const float4*>(vf)[v * NV_P + lane];
        cnt = vnp[v];
    }
    while (v < V) {
        int vn = v + nw;
        float4 ptn; int cntn;
        if (vn < V) {
            ptn  = reinterpret_cast<const float4*>(vf)[vn * NV_P + lane];
            cntn = vnp[vn];
        }

        // ---- stats: masked raw moments (per lane, once per voxel) ----
        float mk = (lane < cnt) ? 1.f : 0.f;
        unsigned long long mm  = pk2(mk, mk);
        unsigned long long pxy = pk2(pt.x, pt.y);
        unsigned long long pzw = pk2(pt.z, pt.w);
        unsigned long long mxy = mul2(pxy, mm);
        unsigned long long mzw = mul2(pzw, mm);
        m1a = add2(m1a, mxy);
        m1b = add2(m1b, mzw);
        unsigned long long bx  = pk2(pt.x, pt.x);
        unsigned long long by  = pk2(pt.y, pt.y);
        unsigned long long bz  = pk2(pt.z, pt.z);
        unsigned long long byw = pk2(pt.y, pt.w);
        M2a = fma2(bx, mxy, M2a);              // (xx, xy)
        M2b = fma2(bx, mzw, M2b);              // (xz, xw)
        M2c = fma2(by, mzw, M2c);              // (yz, yw)
        M2d = fma2(bz, mzw, M2d);              // (zz, zw)
        M2e = fma2(byw, mul2(byw, mm), M2e);   // (yy, ww)

        // ---- per-voxel sums via fixed-point REDUX ----
        float sx = redux_sumf(pt.x);
        float sy = redux_sumf(pt.y);
        float sz = redux_sumf(pt.z);
        float a0, a1, a2, a3;
        unpk2(mxy, a0, a1); unpk2(mzw, a2, a3);    // masked components
        float msx = redux_sumf(a0);
        float msy = redux_sumf(a1);
        float msz = redux_sumf(a2);
        float msw = redux_sumf(a3);
        if (lane == 0) {
            float inv = 1.0f / (float)cnt;
            g_mean[v] = make_float4(sx * inv, sy * inv, sz * inv, (float)cnt);
            g_m1[v]   = make_float4(msx, msy, msz, msw);
        }

        // ---- stage pair-transposed point data ----
        __syncwarp();
        {
            float px = __shfl_xor_sync(0xffffffffu, pt.x, 1);
            float py = __shfl_xor_sync(0xffffffffu, pt.y, 1);
            float pz = __shfl_xor_sync(0xffffffffu, pt.z, 1);
            float pw = __shfl_xor_sync(0xffffffffu, pt.w, 1);
            float4 st;
            if (lane & 1) st = make_float4(pz, pt.z, pw, pt.w);
            else          st = make_float4(pt.x, px, pt.y, py);
            reinterpret_cast<float4*>(msh)[lane] = st;
        }
        __syncwarp();

        // ---- max over points of s*(u . p), two points per iteration ----
        float mA = -3.402823466e38f, mB = -3.402823466e38f;
        const ulonglong2* pp = reinterpret_cast<const ulonglong2*>(msh);
        int npair = cnt >> 1;
        for (int k = 0; k < npair; k++) {
            ulonglong2 q = pp[2 * k];
            ulonglong2 r = pp[2 * k + 1];
            unsigned long long aA = mul2(q.x, uA0);
            unsigned long long aB = mul2(q.x, uB0);
            aA = fma2(q.y, uA1, aA);  aB = fma2(q.y, uB1, aB);
            aA = fma2(r.x, uA2, aA);  aB = fma2(r.x, uB2, aB);
            aA = fma2(r.y, uA3, aA);  aB = fma2(r.y, uB3, aB);
            float t0, t1;
            unpk2(aA, t0, t1); mA = fmaxf(mA, fmaxf(t0, t1));
            unpk2(aB, t0, t1); mB = fmaxf(mB, fmaxf(t0, t1));
        }
        if (cnt & 1) {
            ulonglong2 q = pp[2 * npair];
            ulonglong2 r = pp[2 * npair + 1];
            unsigned long long aA = mul2(q.x, uA0);
            unsigned long long aB = mul2(q.x, uB0);
            aA = fma2(q.y, uA1, aA);  aB = fma2(q.y, uB1, aB);
            aA = fma2(r.x, uA2, aA);  aB = fma2(r.x, uB2, aB);
            aA = fma2(r.y, uA3, aA);  aB = fma2(r.y, uB3, aB);
            float t0, t1;
            unpk2(aA, t0, t1); mA = fmaxf(mA, t0);
            unpk2(aB, t0, t1); mB = fmaxf(mB, t0);
        }

        reinterpret_cast<float2*>(out)[v * 32 + lane] = make_float2(mA, mB);  // raw
        v = vn; pt = ptn; cnt = cntn;
    }

    // ---- block reduce the 14 global moments ----
#pragma unroll
    for (int off = 16; off; off >>= 1) {
        M2a = add2(M2a, __shfl_xor_sync(0xffffffffu, M2a, off));
        M2b = add2(M2b, __shfl_xor_sync(0xffffffffu, M2b, off));
        M2c = add2(M2c, __shfl_xor_sync(0xffffffffu, M2c, off));
        M2d = add2(M2d, __shfl_xor_sync(0xffffffffu, M2d, off));
        M2e = add2(M2e, __shfl_xor_sync(0xffffffffu, M2e, off));
        m1a = add2(m1a, __shfl_xor_sync(0xffffffffu, m1a, off));
        m1b = add2(m1b, __shfl_xor_sync(0xffffffffu, m1b, off));
    }
    if (lane == 0) {
        float xx, xy, xz, xw_, yy, ww, yz, yw, zz, zw, m1x, m1y, m1z, m1w;
        unpk2(M2a, xx, xy);  unpk2(M2b, xz, xw_);
        unpk2(M2e, yy, ww);  unpk2(M2c, yz, yw);
        unpk2(M2d, zz, zw);
        unpk2(m1a, m1x, m1y); unpk2(m1b, m1z, m1w);
        red[0 * 8 + wib] = xx;  red[1 * 8 + wib] = xy;
        red[2 * 8 + wib] = xz;  red[3 * 8 + wib] = xw_;
        red[4 * 8 + wib] = yy;  red[5 * 8 + wib] = yz;
        red[6 * 8 + wib] = yw;  red[7 * 8 + wib] = zz;
        red[8 * 8 + wib] = zw;  red[9 * 8 + wib] = ww;
        red[10 * 8 + wib] = m1x; red[11 * 8 + wib] = m1y;
        red[12 * 8 + wib] = m1z; red[13 * 8 + wib] = m1w;
    }
    __syncthreads();
    int t = threadIdx.x;
    if (t < 14) {
        float s = 0.f;
#pragma unroll
        for (int w = 0; w < 8; w++) s += red[t * 8 + w];
        g_part[t * GP_W + blockIdx.x] = s;
    }
}

// ---------------- k1b: per-voxel q-outer-product moments ----------------
__global__ __launch_bounds__(256) void k1b(const int* __restrict__ coords, int V)
{
    float X[24], Y[21], Z[6];
#pragma unroll
    for (int i = 0; i < 24; i++) X[i] = 0.f;
#pragma unroll
    for (int i = 0; i < 21; i++) Y[i] = 0.f;
#pragma unroll
    for (int i = 0; i < 6; i++) Z[i] = 0.f;

    for (int v = blockIdx.x * blockDim.x + threadIdx.x; v < V; v += K1B_BLOCKS * 256) {
        float4 me = g_mean[v];
        float4 m1 = g_m1[v];
        int4 c4 = reinterpret_cast<const int4*>(coords)[v];
        float q[6];
        q[0] = me.x; q[1] = me.y; q[2] = me.z;
        q[3] = (float)c4.w * C_VX + C_XOFF;
        q[4] = (float)c4.z * C_VY + C_YOFF;
        q[5] = (float)c4.y * C_VZ + C_ZOFF;
        float m1_[4] = {m1.x, m1.y, m1.z, m1.w};
        float fc = me.w;
#pragma unroll
        for (int a = 0; a < 4; a++)
#pragma unroll
            for (int k = 0; k < 6; k++)
                X[a * 6 + k] = fmaf(m1_[a], q[k], X[a * 6 + k]);
        int idx = 0;
#pragma unroll
        for (int k = 0; k < 6; k++) {
            float fq = fc * q[k];
#pragma unroll
            for (int l = k; l < 6; l++) { Y[idx] = fmaf(fq, q[l], Y[idx]); idx++; }
            Z[k] += fq;
        }
    }

    // warp butterfly all 51
#pragma unroll
    for (int i = 0; i < 24; i++)
#pragma unroll
        for (int off = 16; off; off >>= 1) X[i] += __shfl_xor_sync(0xffffffffu, X[i], off);
#pragma unroll
    for (int i = 0; i < 21; i++)
#pragma unroll
        for (int off = 16; off; off >>= 1) Y[i] += __shfl_xor_sync(0xffffffffu, Y[i], off);
#pragma unroll
    for (int i = 0; i < 6; i++)
#pragma unroll
        for (int off = 16; off; off >>= 1) Z[i] += __shfl_xor_sync(0xffffffffu, Z[i], off);

    __shared__ float red[51 * 8];
    int lane = threadIdx.x & 31, wib = threadIdx.x >> 5;
    if (lane == 0) {
#pragma unroll
        for (int i = 0; i < 24; i++) red[i * 8 + wib] = X[i];
#pragma unroll
        for (int i = 0; i < 21; i++) red[(24 + i) * 8 + wib] = Y[i];
#pragma unroll
        for (int i = 0; i < 6; i++)  red[(45 + i) * 8 + wib] = Z[i];
    }
    __syncthreads();
    int t = threadIdx.x;
    if (t < 51) {
        float s = 0.f;
#pragma unroll
        for (int w = 0; w < 8; w++) s += red[t * 8 + w];
        g_part[(14 + t) * GP_W + blockIdx.x] = s;
    }
}

// ---------------- kred: reduce per-block partials in double ----------------
__global__ void kred_stats() {
    int b = blockIdx.x;
    int nb = (b < 14) ? KF_BLOCKS : K1B_BLOCKS;
    double s = 0.0;
    for (int i = threadIdx.x; i < nb; i += blockDim.x)
        s += (double)g_part[b * GP_W + i];
    __shared__ double sd[256];
    sd[threadIdx.x] = s;
    __syncthreads();
    for (int off = 128; off; off >>= 1) {
        if (threadIdx.x < off) sd[threadIdx.x] += sd[threadIdx.x + off];
        __syncthreads();
    }
    if (threadIdx.x == 0) g_stat[b] = sd[0];
}

// ---------------- k2: assemble S from raw moments (R11-validated); emit kE table ----------------
__global__ void k2_coef(const float* __restrict__ W, const float* __restrict__ gamma,
                        const float* __restrict__ beta, double invN)
{
    int o = threadIdx.x;
    if (o >= 64) return;
    double M2v[10], m1v[4], Xv[24], Yv[21], zv[6];
#pragma unroll
    for (int i = 0; i < 10; i++) M2v[i] = g_stat[i];
#pragma unroll
    for (int a = 0; a < 4; a++) m1v[a] = g_stat[10 + a];
#pragma unroll
    for (int i = 0; i < 24; i++) Xv[i] = g_stat[14 + i];
#pragma unroll
    for (int i = 0; i < 21; i++) Yv[i] = g_stat[38 + i];
#pragma unroll
    for (int k = 0; k < 6; k++) zv[k] = g_stat[59 + k];

    const int amap[10] = {0, 1, 2, 3, 0, 1, 2, 0, 1, 2};
    const int m2off[4] = {0, 4, 7, 9};

    double w[10];
#pragma unroll
    for (int c = 0; c < 10; c++) w[c] = (double)W[o * 10 + c];

    double mean = 0.0;
#pragma unroll
    for (int i = 0; i < 10; i++) {
        double mi = m1v[amap[i]] - (i >= 4 ? zv[i - 4] : 0.0);
        mean += w[i] * mi;
    }
    mean *= invN;

    double e2 = 0.0;
    for (int i = 0; i < 10; i++) {
        for (int j = 0; j < 10; j++) {
            int a = amap[i], b = amap[j];
            int lo = a < b ? a : b, hi = a < b ? b : a;
            double S = M2v[m2off[lo] + (hi - lo)];
            if (j >= 4) S -= Xv[a * 6 + (j - 4)];
            if (i >= 4) S -= Xv[b * 6 + (i - 4)];
            if (i >= 4 && j >= 4) {
                int k = i - 4, l = j - 4;
                int klo = k < l ? k : l, khi = k < l ? l : k;
                int yoff = klo * 6 - (klo * (klo - 1)) / 2;
                S += Yv[yoff + (khi - klo)];
            }
            e2 += w[i] * w[j] * S;
        }
    }
    e2 *= invN;
    double var = e2 - mean * mean;
    float ga = gamma[o];
    float a = ga * rsqrtf((float)var + BN_EPS);
    float b = beta[o] - (float)mean * a;
    float s = (ga >= 0.f) ? 1.f : -1.f;
    // kE table: (s*w4, s*w5, s*w6, s*w7), (s*w8, s*w9, |a|, b)
    g_kw4[o * 2]     = make_float4(s * (float)w[4], s * (float)w[5], s * (float)w[6], s * (float)w[7]);
    g_kw4[o * 2 + 1] = make_float4(s * (float)w[8], s * (float)w[9], fabsf(a), b);
}

// ---------------- kE: in-place out = relu(|a|*(m + s*base) + b) ----------------
__global__ __launch_bounds__(256) void kE(const int* __restrict__ coords,
                                          float* __restrict__ out, int V)
{
    int tid = blockIdx.x * blockDim.x + threadIdx.x;
    if (tid >= V * 32) return;
    int v = tid >> 5, lane = tid & 31;
    float2 m = reinterpret_cast<float2*>(out)[tid];
    float4 me = g_mean[v];                                  // (mx,my,mz,cnt) broadcast
    int4 c4 = reinterpret_cast<const int4*>(coords)[v];     // broadcast
    float4 tA0 = g_kw4[(2 * lane) * 2];
    float4 tA1 = g_kw4[(2 * lane) * 2 + 1];
    float4 tB0 = g_kw4[(2 * lane + 1) * 2];
    float4 tB1 = g_kw4[(2 * lane + 1) * 2 + 1];
    float cx = (float)c4.w * C_VX + C_XOFF;
    float cy = (float)c4.z * C_VY + C_YOFF;
    float cz = (float)c4.y * C_VZ + C_ZOFF;
    // s*base = -(mean . s*w[4:7]) - (center . s*w[7:10])
    float sbA = -(me.x * tA0.x + me.y * tA0.y + me.z * tA0.z
                + cx * tA0.w + cy * tA1.x + cz * tA1.y);
    float sbB = -(me.x * tB0.x + me.y * tB0.y + me.z * tB0.z
                + cx * tB0.w + cy * tB1.x + cz * tB1.y);
    float xA = m.x + sbA;
    float xB = m.y + sbB;
    if (me.w < 31.5f) { xA = fmaxf(xA, 0.f); xB = fmaxf(xB, 0.f); }  // masked rows: x = 0
    float rA = fmaxf(fmaf(tA1.z, xA, tA1.w), 0.f);
    float rB = fmaxf(fmaf(tB1.z, xB, tB1.w), 0.f);
    reinterpret_cast<float2*>(out)[tid] = make_float2(rA, rB);
}

extern "C" void kernel_launch(void* const* d_in, const int* in_sizes, int n_in,
                              void* d_out, int out_size) {
    const float* vf     = (const float*)d_in[0];
    const int*   vnp    = (const int*)d_in[1];
    const int*   coords = (const int*)d_in[2];
    const float* W      = (const float*)d_in[3];
    const float* gamma  = (const float*)d_in[4];
    const float* beta   = (const float*)d_in[5];
    float* out = (float*)d_out;
    int V = in_sizes[1];   // voxel_num_points element count

    kF<<<KF_BLOCKS, KF_THREADS>>>(vf, vnp, W, gamma, out, V);
    k1b<<<K1B_BLOCKS, 256>>>(coords, V);
    kred_stats<<<NSTAT, 256>>>();
    double invN = 1.0 / ((double)V * (double)NV_P);
    k2_coef<<<1, 64>>>(W, gamma, beta, invN);
    int nE = (V * 32 + 255) / 256;
    kE<<<nE, 256>>>(coords, out, V);
}

// round 13
// speedup vs baseline: 1.3292x; 1.3292x over previous
#include <cuda_runtime.h>
#include <cstdint>

#define NV_P   32
#define C_VX   0.16f
#define C_VY   0.16f
#define C_VZ   4.0f
#define C_XOFF 0.08f
#define C_YOFF -39.6f
#define C_ZOFF -1.0f
#define BN_EPS 1e-3f

#define VPB        96      // voxels per block == threads per block (k1)
#define K1_MAXB    1376
#define K3_BLOCKS  592
#define K3_THREADS 256
#define NSTAT      65
// stat layout: [0..9] M2 (xx,xy,xz,xw,yy,yz,yw,zz,zw,ww)  [10..13] m1(x,y,z,w)
//              [14..37] X[a][k]=m1[a]*q[k]  [38..58] Y tri = cnt*q[k]*q[l]  [59..64] cnt*q[k]
// q = (mx,my,mz,cx,cy,cz)

// -------- global scratch (allocation-free rule: __device__ globals) --------
__device__ float  g_part[NSTAT * K1_MAXB];   // [stat][block]
__device__ double g_stat[NSTAT];
__device__ float  g_ab[128];                 // |a|[0..63], b[64..127]
__device__ float4 g_mc4[131072];             // per-voxel (mx,my,mz,cx)
__device__ float2 g_c2[131072];              // per-voxel (cy,cz)

// ---------------- packed f32x2 helpers ----------------
__device__ __forceinline__ unsigned long long pk2(float lo, float hi) {
    unsigned long long r;
    asm("mov.b64 %0, {%1, %2};" : "=l"(r) : "f"(lo), "f"(hi));
    return r;
}
__device__ __forceinline__ void unpk2(unsigned long long x, float& lo, float& hi) {
    asm("mov.b64 {%0, %1}, %2;" : "=f"(lo), "=f"(hi) : "l"(x));
}
__device__ __forceinline__ unsigned long long fma2(unsigned long long a, unsigned long long b, unsigned long long c) {
    unsigned long long d;
    asm("fma.rn.f32x2 %0, %1, %2, %3;" : "=l"(d) : "l"(a), "l"(b), "l"(c));
    return d;
}
__device__ __forceinline__ unsigned long long add2(unsigned long long a, unsigned long long b) {
    unsigned long long d;
    asm("add.rn.f32x2 %0, %1, %2;" : "=l"(d) : "l"(a), "l"(b));
    return d;
}
__device__ __forceinline__ unsigned long long mul2(unsigned long long a, unsigned long long b) {
    unsigned long long d;
    asm("mul.rn.f32x2 %0, %1, %2;" : "=l"(d) : "l"(a), "l"(b));
    return d;
}
__device__ __forceinline__ uint32_t smem_u32(const void* p) {
    uint32_t a;
    asm("{ .reg .u64 t; cvta.to.shared.u64 t, %1; cvt.u32.u64 %0, t; }" : "=r"(a) : "l"(p));
    return a;
}
__device__ __forceinline__ void cpa16(uint32_t dst, const void* src) {
    asm volatile("cp.async.cg.shared.global [%0], [%1], 16;" :: "r"(dst), "l"(src) : "memory");
}
__device__ __forceinline__ float4 lds128f(uint32_t a) {
    float4 r;
    asm volatile("ld.shared.v4.f32 {%0,%1,%2,%3}, [%4];"
                 : "=f"(r.x), "=f"(r.y), "=f"(r.z), "=f"(r.w) : "r"(a));
    return r;
}

// ---------------- k1v2: voxel-per-thread raw-moment stats (R11 verbatim) ----------------
__global__ __launch_bounds__(VPB) void k1_stats(
    const float* __restrict__ vf, const int* __restrict__ vnp,
    const int* __restrict__ coords, int V)
{
    __shared__ __align__(16) unsigned char sbuf[VPB * NV_P * 16];   // 48 KB
    const int t = threadIdx.x;
    const int vbase = blockIdx.x * VPB;
    const uint32_t sb = smem_u32(sbuf);

    // ---- stage VPB voxels, swizzled [point][voxel] ----
    const int total = min(VPB, V - vbase) * NV_P;
    const float4* gsrc = reinterpret_cast<const float4*>(vf) + (size_t)vbase * NV_P;
#pragma unroll
    for (int k = 0; k < NV_P; k++) {
        int g = k * VPB + t;
        int gc = min(g, total - 1);           // clamp: always finite data in smem
        int p = gc & 31, vv = gc >> 5;
        uint32_t dst = sb + ((uint32_t)((p * VPB + vv) << 4) ^ (uint32_t)((p & 7) << 4));
        if (g < total || gc != g)
            cpa16(dst, gsrc + gc);
    }
    asm volatile("cp.async.commit_group;" ::: "memory");
    asm volatile("cp.async.wait_group 0;" ::: "memory");
    __syncthreads();

    const int vg = vbase + t;
    const bool active = vg < V;
    int cnt = 1; int4 c4 = make_int4(0, 0, 0, 0);
    if (active) {
        cnt = vnp[vg];
        c4  = reinterpret_cast<const int4*>(coords)[vg];
    }

    // ---- per-thread masked raw moments over 32 points ----
    unsigned long long M2a = 0ull, M2b = 0ull, M2c = 0ull, M2d = 0ull, M2e = 0ull;
    unsigned long long m1a = 0ull, m1b = 0ull, sxy = 0ull;
    float sz = 0.f;
#pragma unroll
    for (int p = 0; p < NV_P; p++) {
        uint32_t addr = sb + ((uint32_t)(((p * VPB + t) << 4)) ^ (uint32_t)((p & 7) << 4));
        float4 pt = lds128f(addr);
        unsigned long long pxy = pk2(pt.x, pt.y);
        unsigned long long pzw = pk2(pt.z, pt.w);
        sxy = add2(sxy, pxy);                 // unmasked sums (mean over ALL 32)
        sz += pt.z;
        float mk = (p < cnt) ? 1.f : 0.f;
        unsigned long long mm  = pk2(mk, mk);
        unsigned long long mxy = mul2(pxy, mm);
        unsigned long long mzw = mul2(pzw, mm);
        m1a = add2(m1a, mxy);
        m1b = add2(m1b, mzw);
        unsigned long long bx  = pk2(pt.x, pt.x);
        unsigned long long by  = pk2(pt.y, pt.y);
        unsigned long long bz  = pk2(pt.z, pt.z);
        unsigned long long byw = pk2(pt.y, pt.w);
        M2a = fma2(bx, mxy, M2a);             // (xx, xy)
        M2b = fma2(bx, mzw, M2b);             // (xz, xw)
        M2c = fma2(by, mzw, M2c);             // (yz, yw)
        M2d = fma2(bz, mzw, M2d);             // (zz, zw)
        M2e = fma2(byw, mul2(byw, mm), M2e);  // (yy, ww)
    }

    // ---- per-voxel q terms + write to reduction smem ----
    __syncthreads();                          // staging buffer now dead; reuse as red[]
    float* red = reinterpret_cast<float*>(sbuf);   // [NSTAT][VPB+1]
    {
        float xx, xy; unpk2(M2a, xx, xy);
        float xz, xw; unpk2(M2b, xz, xw);
        float yz, yw; unpk2(M2c, yz, yw);
        float zz, zw; unpk2(M2d, zz, zw);
        float yy, ww; unpk2(M2e, yy, ww);
        float m1x, m1y; unpk2(m1a, m1x, m1y);
        float m1z, m1w; unpk2(m1b, m1z, m1w);
        float sx, sy; unpk2(sxy, sx, sy);
        float inv = 1.0f / (float)cnt;
        float mx = sx * inv, my = sy * inv, mz = sz * inv;
        float cx = (float)c4.w * C_VX + C_XOFF;
        float cy = (float)c4.z * C_VY + C_YOFF;
        float cz = (float)c4.y * C_VZ + C_ZOFF;
        if (active) {
            g_mc4[vg] = make_float4(mx, my, mz, cx);
            g_c2[vg]  = make_float2(cy, cz);
        }
        float q_[6]  = {mx, my, mz, cx, cy, cz};
        float m1_[4] = {m1x, m1y, m1z, m1w};
        float fc = (float)cnt;
#define STR(i, val) red[(i) * (VPB + 1) + t] = active ? (val) : 0.f
        STR(0, xx); STR(1, xy); STR(2, xz); STR(3, xw); STR(4, yy);
        STR(5, yz); STR(6, yw); STR(7, zz); STR(8, zw); STR(9, ww);
        STR(10, m1x); STR(11, m1y); STR(12, m1z); STR(13, m1w);
#pragma unroll
        for (int a = 0; a < 4; a++)
#pragma unroll
            for (int k = 0; k < 6; k++)
                STR(14 + a * 6 + k, m1_[a] * q_[k]);
        int idx = 38;
#pragma unroll
        for (int k = 0; k < 6; k++)
#pragma unroll
            for (int l = k; l < 6; l++) { STR(idx, fc * q_[k] * q_[l]); idx++; }
#pragma unroll
        for (int k = 0; k < 6; k++)
            STR(59 + k, fc * q_[k]);
#undef STR
    }
    __syncthreads();

    // ---- block reduce: thread s sums stat s over VPB threads ----
    if (t < NSTAT) {
        float acc = 0.f;
#pragma unroll 8
        for (int i = 0; i < VPB; i++) acc += red[t * (VPB + 1) + i];
        g_part[t * K1_MAXB + blockIdx.x] = acc;
    }
}

// ---------------- kred: reduce per-block partials in double ----------------
__global__ void kred_stats(int nb) {
    int b = blockIdx.x;
    double s = 0.0;
    for (int i = threadIdx.x; i < nb; i += blockDim.x)
        s += (double)g_part[b * K1_MAXB + i];
    __shared__ double sd[256];
    sd[threadIdx.x] = s;
    __syncthreads();
    for (int off = 128; off; off >>= 1) {
        if (threadIdx.x < off) sd[threadIdx.x] += sd[threadIdx.x + off];
        __syncthreads();
    }
    if (threadIdx.x == 0) g_stat[b] = sd[0];
}

// ---------------- k2: shared-assembled S matrix; per-channel w^T S w ----------------
__global__ void k2_coef(const float* __restrict__ W, const float* __restrict__ gamma,
                        const float* __restrict__ beta, double invN)
{
    __shared__ double Ssh[10][10];
    __shared__ double msh[10];
    const int t = threadIdx.x;

    // threads 0..54: one upper-tri S entry each (channel-independent!)
    if (t < 55) {
        // t -> (i,j), i<=j
        int i = 0, tt = t;
        while (tt >= 10 - i) { tt -= 10 - i; i++; }
        int j = i + tt;
        const int amap[10] = {0, 1, 2, 3, 0, 1, 2, 0, 1, 2};
        const int m2off[4] = {0, 4, 7, 9};
        int a = amap[i], b = amap[j];
        int lo = a < b ? a : b, hi = a < b ? b : a;
        double S = g_stat[m2off[lo] + (hi - lo)];
        if (j >= 4) S -= g_stat[14 + a * 6 + (j - 4)];
        if (i >= 4) S -= g_stat[14 + b * 6 + (i - 4)];
        if (i >= 4 && j >= 4) {
            int k = i - 4, l = j - 4;
            int klo = k < l ? k : l, khi = k < l ? l : k;
            int yoff = klo * 6 - (klo * (klo - 1)) / 2;
            S += g_stat[38 + yoff + (khi - klo)];
        }
        Ssh[i][j] = S;
        Ssh[j][i] = S;
    }
    // threads 64..73: mean vector entries
    if (t >= 64 && t < 74) {
        int i = t - 64;
        const int amap[10] = {0, 1, 2, 3, 0, 1, 2, 0, 1, 2};
        double mi = g_stat[10 + amap[i]] - (i >= 4 ? g_stat[59 + (i - 4)] : 0.0);
        msh[i] = mi;
    }
    __syncthreads();

    if (t >= 64) return;
    int o = t;
    double w[10];
#pragma unroll
    for (int c = 0; c < 10; c++) w[c] = (double)W[o * 10 + c];
    double mean = 0.0;
#pragma unroll
    for (int i = 0; i < 10; i++) mean += w[i] * msh[i];
    mean *= invN;
    double e2 = 0.0;
#pragma unroll
    for (int i = 0; i < 10; i++) {
        double acc = 0.0;
#pragma unroll
        for (int j = 0; j < 10; j++) acc += w[j] * Ssh[i][j];
        e2 += w[i] * acc;
    }
    e2 *= invN;
    double var = e2 - mean * mean;
    float a = gamma[o] * rsqrtf((float)var + BN_EPS);
    float b = beta[o] - (float)mean * a;
    g_ab[o]      = fabsf(a);                 // k3 folds sign(a)=sign(gamma) itself
    g_ab[64 + o] = b;
}

// ---------------- k3: point-pair packed max of s*(u.p); final affine+relu (R9 verbatim) ----------------
__global__ __launch_bounds__(K3_THREADS, 4) void k3_out(
    const float* __restrict__ vf, const int* __restrict__ vnp,
    const float* __restrict__ W, const float* __restrict__ gamma,
    float* __restrict__ out, int V)
{
    __shared__ __align__(16) float sh[8 * NV_P * 4];
    const int lane = threadIdx.x & 31;
    const int wib  = threadIdx.x >> 5;
    const int gw   = (blockIdx.x * blockDim.x + threadIdx.x) >> 5;
    const int nw   = (gridDim.x * blockDim.x) >> 5;
    float* msh = sh + wib * (NV_P * 4);

    const float* wA = W + (2 * lane) * 10;
    const float* wB = wA + 10;
    float sA = (gamma[2 * lane]     >= 0.f) ? 1.f : -1.f;
    float sB = (gamma[2 * lane + 1] >= 0.f) ? 1.f : -1.f;
    float uA0s = sA * (wA[0] + wA[4] + wA[7]);
    float uA1s = sA * (wA[1] + wA[5] + wA[8]);
    float uA2s = sA * (wA[2] + wA[6] + wA[9]);
    float uA3s = sA * wA[3];
    float uB0s = sB * (wB[0] + wB[4] + wB[7]);
    float uB1s = sB * (wB[1] + wB[5] + wB[8]);
    float uB2s = sB * (wB[2] + wB[6] + wB[9]);
    float uB3s = sB * wB[3];
    unsigned long long uA0 = pk2(uA0s, uA0s), uA1 = pk2(uA1s, uA1s);
    unsigned long long uA2 = pk2(uA2s, uA2s), uA3 = pk2(uA3s, uA3s);
    unsigned long long uB0 = pk2(uB0s, uB0s), uB1 = pk2(uB1s, uB1s);
    unsigned long long uB2 = pk2(uB2s, uB2s), uB3 = pk2(uB3s, uB3s);

    float2 av = reinterpret_cast<const float2*>(g_ab)[lane];
    float2 bv = reinterpret_cast<const float2*>(g_ab + 64)[lane];

    int v = gw;
    float4 pt; int cnt;
    if (v < V) {
        pt  = reinterpret_cast<const float4*>(vf)[v * NV_P + lane];
        cnt = vnp[v];
    }
    while (v < V) {
        int vn = v + nw;
        float4 ptn; int cntn;
        if (vn < V) {
            ptn  = reinterpret_cast<const float4*>(vf)[vn * NV_P + lane];
            cntn = vnp[vn];
        }
        float4 mc = g_mc4[v];
        float2 c2 = g_c2[v];
        float2 w4 = make_float2(wA[4], wB[4]);
        float2 w5 = make_float2(wA[5], wB[5]);
        float2 w6 = make_float2(wA[6], wB[6]);
        float2 w7 = make_float2(wA[7], wB[7]);
        float2 w8 = make_float2(wA[8], wB[8]);
        float2 w9 = make_float2(wA[9], wB[9]);

        __syncwarp();
        {
            float px = __shfl_xor_sync(0xffffffffu, pt.x, 1);
            float py = __shfl_xor_sync(0xffffffffu, pt.y, 1);
            float pz = __shfl_xor_sync(0xffffffffu, pt.z, 1);
            float pw = __shfl_xor_sync(0xffffffffu, pt.w, 1);
            float4 st;
            if (lane & 1) st = make_float4(pz, pt.z, pw, pt.w);
            else          st = make_float4(pt.x, px, pt.y, py);
            reinterpret_cast<float4*>(msh)[lane] = st;
        }
        __syncwarp();

        float mA = -3.402823466e38f, mB = -3.402823466e38f;
        const ulonglong2* pp = reinterpret_cast<const ulonglong2*>(msh);
        int npair = cnt >> 1;
        for (int k = 0; k < npair; k++) {
            ulonglong2 q = pp[2 * k];
            ulonglong2 r = pp[2 * k + 1];
            unsigned long long aA = mul2(q.x, uA0);
            unsigned long long aB = mul2(q.x, uB0);
            aA = fma2(q.y, uA1, aA);  aB = fma2(q.y, uB1, aB);
            aA = fma2(r.x, uA2, aA);  aB = fma2(r.x, uB2, aB);
            aA = fma2(r.y, uA3, aA);  aB = fma2(r.y, uB3, aB);
            float t0, t1;
            unpk2(aA, t0, t1); mA = fmaxf(mA, fmaxf(t0, t1));
            unpk2(aB, t0, t1); mB = fmaxf(mB, fmaxf(t0, t1));
        }
        if (cnt & 1) {
            ulonglong2 q = pp[2 * npair];
            ulonglong2 r = pp[2 * npair + 1];
            unsigned long long aA = mul2(q.x, uA0);
            unsigned long long aB = mul2(q.x, uB0);
            aA = fma2(q.y, uA1, aA);  aB = fma2(q.y, uB1, aB);
            aA = fma2(r.x, uA2, aA);  aB = fma2(r.x, uB2, aB);
            aA = fma2(r.y, uA3, aA);  aB = fma2(r.y, uB3, aB);
            float t0, t1;
            unpk2(aA, t0, t1); mA = fmaxf(mA, t0);
            unpk2(aB, t0, t1); mB = fmaxf(mB, t0);
        }

        float baA = -(mc.x * w4.x + mc.y * w5.x + mc.z * w6.x + mc.w * w7.x + c2.x * w8.x + c2.y * w9.x);
        float baB = -(mc.x * w4.y + mc.y * w5.y + mc.z * w6.y + mc.w * w7.y + c2.x * w8.y + c2.y * w9.y);
        float xA = mA + sA * baA;
        float xB = mB + sB * baB;
        if (cnt < NV_P) { xA = fmaxf(xA, 0.f); xB = fmaxf(xB, 0.f); }
        float r0o = fmaxf(fmaf(av.x, xA, bv.x), 0.f);
        float r1o = fmaxf(fmaf(av.y, xB, bv.y), 0.f);
        reinterpret_cast<float2*>(out)[v * 32 + lane] = make_float2(r0o, r1o);

        v = vn; pt = ptn; cnt = cntn;
    }
}

extern "C" void kernel_launch(void* const* d_in, const int* in_sizes, int n_in,
                              void* d_out, int out_size) {
    const float* vf     = (const float*)d_in[0];
    const int*   vnp    = (const int*)d_in[1];
    const int*   coords = (const int*)d_in[2];
    const float* W      = (const float*)d_in[3];
    const float* gamma  = (const float*)d_in[4];
    const float* beta   = (const float*)d_in[5];
    float* out = (float*)d_out;
    int V = in_sizes[1];   // voxel_num_points element count

    int nb = (V + VPB - 1) / VPB;
    k1_stats<<<nb, VPB>>>(vf, vnp, coords, V);
    kred_stats<<<NSTAT, 256>>>(nb);
    double invN = 1.0 / ((double)V * (double)NV_P);
    k2_coef<<<1, 128>>>(W, gamma, beta, invN);
    k3_out<<<K3_BLOCKS, K3_THREADS>>>(vf, vnp, W, gamma, out, V);
}